// round 1
// baseline (speedup 1.0000x reference)
#include <cuda_runtime.h>
#include <math.h>

// Problem constants (fixed by the dataset)
#define BB   4
#define NN   2048
#define DD   512          // model dim == inner dim
#define HH   8
#define DH   64
#define WIN  64           // truncation window: r^64 <= 3.4e-8, negligible vs 1e-3 tol
#define TI   32           // i-tile per attention block

// Scratch (device globals; no allocation allowed)
__device__ float g_V   [(size_t)BB * NN * DD];   // (b, n, h*dh) layout
__device__ float g_attn[(size_t)BB * NN * DD];   // (b, n, h*dh) layout
__device__ float g_r   [(size_t)BB * HH * NN];   // decay rate per (b,h,i)

// ---------------------------------------------------------------------------
// Kernel 1: r[b,h,i] = exp(-1 / (exp(sigmoid(x[b,i,:] . W_sigma[:,h] + b_sigma[h])) + 1))
// One block per (b,i) row; warp h computes head h.
// ---------------------------------------------------------------------------
__global__ void sigma_kernel(const float* __restrict__ x,
                             const float* __restrict__ Ws,
                             const float* __restrict__ bs)
{
    int bi = blockIdx.x;               // b*NN + i
    __shared__ float xs[DD];
    const float* xrow = x + (size_t)bi * DD;
    for (int c = threadIdx.x; c < DD; c += blockDim.x) xs[c] = xrow[c];
    __syncthreads();

    int warp = threadIdx.x >> 5;
    int lane = threadIdx.x & 31;
    if (warp < HH) {
        float s = 0.f;
        #pragma unroll 4
        for (int c = lane; c < DD; c += 32) s += xs[c] * Ws[c * HH + warp];
        #pragma unroll
        for (int o = 16; o > 0; o >>= 1) s += __shfl_xor_sync(0xffffffffu, s, o);
        if (lane == 0) {
            float sig   = 1.f / (1.f + expf(-(s + bs[warp])));
            float denom = expf(sig) + 1.f;
            float r     = expf(-1.f / denom);
            int b = bi / NN, i = bi % NN;
            g_r[((size_t)b * HH + warp) * NN + i] = r;
        }
    }
}

// ---------------------------------------------------------------------------
// Kernel 2/4: C[M,512] = A[M,512] @ Bw[512,512] (+ bias). Classic 128x128x8
// smem-tiled SGEMM, 256 threads, 8x8 microtile, float4 IO. M=8192.
// ---------------------------------------------------------------------------
template<bool BIAS>
__global__ void __launch_bounds__(256, 2)
sgemm512(const float* __restrict__ A, const float* __restrict__ Bw,
         const float* __restrict__ bias, float* __restrict__ C)
{
    const int BM = 128, BN = 128, BK = 8;
    __shared__ float As[BK][BM];
    __shared__ float Bs[BK][BN];

    int tid = threadIdx.x;
    int bx = blockIdx.x;               // N tile (0..3)
    int by = blockIdx.y;               // M tile (0..63)

    int arow  = tid >> 1;              // 0..127
    int acol4 = (tid & 1) * 4;         // 0 or 4
    int brow  = tid >> 5;              // 0..7
    int bcol4 = (tid & 31) * 4;        // 0..124

    int tx = tid & 15;                 // col group
    int ty = tid >> 4;                 // row group

    float acc[8][8];
    #pragma unroll
    for (int m = 0; m < 8; m++)
        #pragma unroll
        for (int n = 0; n < 8; n++) acc[m][n] = 0.f;

    const float* Aptr = A + ((size_t)(by * BM + arow)) * 512 + acol4;
    const float* Bptr = Bw + (size_t)brow * 512 + bx * BN + bcol4;

    for (int k0 = 0; k0 < 512; k0 += BK) {
        float4 a  = *(const float4*)(Aptr + k0);
        float4 bb = *(const float4*)(Bptr + (size_t)k0 * 512);
        As[acol4 + 0][arow] = a.x;
        As[acol4 + 1][arow] = a.y;
        As[acol4 + 2][arow] = a.z;
        As[acol4 + 3][arow] = a.w;
        *(float4*)&Bs[brow][bcol4] = bb;
        __syncthreads();

        #pragma unroll
        for (int k = 0; k < BK; k++) {
            float ar[8], br[8];
            *(float4*)&ar[0] = *(const float4*)&As[k][ty * 8 + 0];
            *(float4*)&ar[4] = *(const float4*)&As[k][ty * 8 + 4];
            *(float4*)&br[0] = *(const float4*)&Bs[k][tx * 8 + 0];
            *(float4*)&br[4] = *(const float4*)&Bs[k][tx * 8 + 4];
            #pragma unroll
            for (int m = 0; m < 8; m++)
                #pragma unroll
                for (int n = 0; n < 8; n++)
                    acc[m][n] += ar[m] * br[n];
        }
        __syncthreads();
    }

    int ccol = bx * BN + tx * 8;
    float bb_[8];
    if (BIAS) {
        #pragma unroll
        for (int n = 0; n < 8; n++) bb_[n] = bias[ccol + n];
    }
    #pragma unroll
    for (int m = 0; m < 8; m++) {
        int row = by * BM + ty * 8 + m;
        float* Crow = C + (size_t)row * 512 + ccol;
        float4 v0, v1;
        v0.x = acc[m][0]; v0.y = acc[m][1]; v0.z = acc[m][2]; v0.w = acc[m][3];
        v1.x = acc[m][4]; v1.y = acc[m][5]; v1.z = acc[m][6]; v1.w = acc[m][7];
        if (BIAS) {
            v0.x += bb_[0]; v0.y += bb_[1]; v0.z += bb_[2]; v0.w += bb_[3];
            v1.x += bb_[4]; v1.y += bb_[5]; v1.z += bb_[6]; v1.w += bb_[7];
        }
        *(float4*)(Crow + 0) = v0;
        *(float4*)(Crow + 4) = v1;
    }
}

// ---------------------------------------------------------------------------
// Kernel 3: windowed exponential-kernel smoothing.
// attn[b,i,h*64+c] = sum_{|i-j|<=WIN, 0<=j<N} r_i^{|i-j|} V[b,j,h*64+c] / Z_i
// Block: one (b,h) x TI-row tile. 512 threads = 32 i x 16 float4 lanes.
// ---------------------------------------------------------------------------
__global__ void __launch_bounds__(512, 2)
attn_kernel()
{
    __shared__ float4 vs[TI + 2 * WIN][DH / 4];   // 160 x 16 float4 = 40 KB

    int bh = blockIdx.y;
    int b  = bh / HH, h = bh % HH;
    int i0 = blockIdx.x * TI;

    const float* Vbase = g_V + (size_t)b * NN * DD + h * DH;

    // Load window rows [i0-WIN, i0+TI+WIN), zero-padded at boundaries
    for (int idx = threadIdx.x; idx < (TI + 2 * WIN) * (DH / 4); idx += blockDim.x) {
        int lr = idx >> 4;            // row in window
        int c  = idx & 15;            // float4 lane
        int j  = i0 - WIN + lr;
        float4 v = make_float4(0.f, 0.f, 0.f, 0.f);
        if (j >= 0 && j < NN) v = *(const float4*)(Vbase + (size_t)j * DD + c * 4);
        vs[lr][c] = v;
    }
    __syncthreads();

    int il = threadIdx.x >> 4;        // 0..31
    int c  = threadIdx.x & 15;        // 0..15
    int i  = i0 + il;
    float r = g_r[(size_t)bh * NN + i];

    int li = il + WIN;
    float4 acc = vs[li][c];
    float  z = 1.f, w = 1.f;

    #pragma unroll
    for (int k = 1; k <= WIN; k++) {
        w *= r;
        float4 vl = vs[li - k][c];    // zero if out of range (padded)
        float4 vr = vs[li + k][c];
        acc.x += w * (vl.x + vr.x);
        acc.y += w * (vl.y + vr.y);
        acc.z += w * (vl.z + vr.z);
        acc.w += w * (vl.w + vr.w);
        z += w * ((float)(i - k >= 0) + (float)(i + k < NN));
    }

    float inv = 1.f / z;
    float4 o = make_float4(acc.x * inv, acc.y * inv, acc.z * inv, acc.w * inv);
    *(float4*)(g_attn + ((size_t)b * NN + i) * DD + h * DH + c * 4) = o;
}

// ---------------------------------------------------------------------------
// Launch
// ---------------------------------------------------------------------------
extern "C" void kernel_launch(void* const* d_in, const int* in_sizes, int n_in,
                              void* d_out, int out_size)
{
    const float* x      = (const float*)d_in[0];
    const float* W_v    = (const float*)d_in[1];
    const float* W_sig  = (const float*)d_in[2];
    const float* b_sig  = (const float*)d_in[3];
    const float* W_out  = (const float*)d_in[4];
    const float* b_out  = (const float*)d_in[5];
    float* out = (float*)d_out;

    float *pV = nullptr, *pAttn = nullptr;
    cudaGetSymbolAddress((void**)&pV,    g_V);
    cudaGetSymbolAddress((void**)&pAttn, g_attn);

    // 1. sigma -> r
    sigma_kernel<<<BB * NN, 256>>>(x, W_sig, b_sig);

    // 2. V = x @ W_v
    {
        dim3 grid(512 / 128, (BB * NN) / 128);
        sgemm512<false><<<grid, 256>>>(x, W_v, nullptr, pV);
    }

    // 3. windowed smoothing
    {
        dim3 grid(NN / TI, BB * HH);
        attn_kernel<<<grid, 512>>>();
    }

    // 4. out = attn @ W_out + b_out
    {
        dim3 grid(512 / 128, (BB * NN) / 128);
        sgemm512<true><<<grid, 256>>>(pAttn, W_out, b_out, out);
    }
}

// round 3
// speedup vs baseline: 1.5179x; 1.5179x over previous
#include <cuda_runtime.h>
#include <cuda_bf16.h>
#include <math.h>
#include <cstdint>

// Problem constants
#define BB   4
#define NN   2048
#define DD   512
#define HH   8
#define DH   64
#define WIN  64
#define TI   32
#define MTOT (BB * NN)          // 8192 rows

// ---------------- scratch (device globals; no allocation allowed) ----------
__device__ __nv_bfloat16 g_xhi [(size_t)MTOT * DD];
__device__ __nv_bfloat16 g_xlo [(size_t)MTOT * DD];
__device__ __nv_bfloat16 g_Wvth[(size_t)DD * DD];   // transposed: [n][k]
__device__ __nv_bfloat16 g_Wvtl[(size_t)DD * DD];
__device__ __nv_bfloat16 g_Woth[(size_t)DD * DD];
__device__ __nv_bfloat16 g_Wotl[(size_t)DD * DD];
__device__ float         g_V   [(size_t)MTOT * DD];
__device__ __nv_bfloat16 g_ahi [(size_t)MTOT * DD];
__device__ __nv_bfloat16 g_alo [(size_t)MTOT * DD];
__device__ float         g_r   [(size_t)BB * HH * NN];

// ---------------- PTX helpers ----------------------------------------------
__device__ __forceinline__ uint32_t smem_u32(const void* p) {
    uint32_t a;
    asm("{ .reg .u64 t; cvta.to.shared.u64 t, %1; cvt.u32.u64 %0, t; }" : "=r"(a) : "l"(p));
    return a;
}
#define CP16(dst, src) \
    asm volatile("cp.async.cg.shared.global [%0], [%1], 16;" :: "r"(dst), "l"(src))
#define CP_COMMIT() asm volatile("cp.async.commit_group;")
#define CP_WAIT(n)  asm volatile("cp.async.wait_group %0;" :: "n"(n))

#define LDSM_X4(r, addr) \
    asm volatile("ldmatrix.sync.aligned.m8n8.x4.shared.b16 {%0,%1,%2,%3}, [%4];" \
        : "=r"((r)[0]), "=r"((r)[1]), "=r"((r)[2]), "=r"((r)[3]) : "r"(addr))

#define MMA16816(d, a, b) \
    asm volatile("mma.sync.aligned.m16n8k16.row.col.f32.bf16.bf16.f32 " \
        "{%0,%1,%2,%3}, {%4,%5,%6,%7}, {%8,%9}, {%0,%1,%2,%3};" \
        : "+f"((d)[0]), "+f"((d)[1]), "+f"((d)[2]), "+f"((d)[3]) \
        : "r"((a)[0]), "r"((a)[1]), "r"((a)[2]), "r"((a)[3]), "r"((b)[0]), "r"((b)[1]))

// ---------------------------------------------------------------------------
// Kernel: split fp32 x -> (hi, lo) bf16 planes.
// ---------------------------------------------------------------------------
__global__ void conv_x_kernel(const float* __restrict__ x)
{
    int i = blockIdx.x * blockDim.x + threadIdx.x;     // float4 index
    if (i >= MTOT * DD / 4) return;
    float4 v = ((const float4*)x)[i];
    __nv_bfloat16 h0 = __float2bfloat16(v.x), h1 = __float2bfloat16(v.y);
    __nv_bfloat16 h2 = __float2bfloat16(v.z), h3 = __float2bfloat16(v.w);
    __nv_bfloat162 hp0; hp0.x = h0; hp0.y = h1;
    __nv_bfloat162 hp1; hp1.x = h2; hp1.y = h3;
    __nv_bfloat162 lp0, lp1;
    lp0.x = __float2bfloat16(v.x - __bfloat162float(h0));
    lp0.y = __float2bfloat16(v.y - __bfloat162float(h1));
    lp1.x = __float2bfloat16(v.z - __bfloat162float(h2));
    lp1.y = __float2bfloat16(v.w - __bfloat162float(h3));
    ((__nv_bfloat162*)g_xhi)[i * 2 + 0] = hp0;
    ((__nv_bfloat162*)g_xhi)[i * 2 + 1] = hp1;
    ((__nv_bfloat162*)g_xlo)[i * 2 + 0] = lp0;
    ((__nv_bfloat162*)g_xlo)[i * 2 + 1] = lp1;
}

// ---------------------------------------------------------------------------
// Kernel: transpose 512x512 fp32 weight -> bf16 hi/lo planes [n][k].
// ---------------------------------------------------------------------------
__global__ void conv_wT_kernel(const float* __restrict__ W,
                               __nv_bfloat16* __restrict__ Th,
                               __nv_bfloat16* __restrict__ Tl)
{
    __shared__ float t[32][33];
    int k0 = blockIdx.x * 32, n0 = blockIdx.y * 32;
    t[threadIdx.y][threadIdx.x] = W[(size_t)(k0 + threadIdx.y) * DD + n0 + threadIdx.x];
    __syncthreads();
    float v = t[threadIdx.x][threadIdx.y];       // W[k0+tx][n0+ty]
    int n = n0 + threadIdx.y, k = k0 + threadIdx.x;
    __nv_bfloat16 h = __float2bfloat16(v);
    Th[(size_t)n * DD + k] = h;
    Tl[(size_t)n * DD + k] = __float2bfloat16(v - __bfloat162float(h));
}

// ---------------------------------------------------------------------------
// Kernel: sigma -> decay rate r[b,h,i]
// ---------------------------------------------------------------------------
__global__ void sigma_kernel(const float* __restrict__ x,
                             const float* __restrict__ Ws,
                             const float* __restrict__ bs)
{
    int bi = blockIdx.x;
    __shared__ float xs[DD];
    const float* xrow = x + (size_t)bi * DD;
    for (int c = threadIdx.x; c < DD; c += blockDim.x) xs[c] = xrow[c];
    __syncthreads();
    int warp = threadIdx.x >> 5, lane = threadIdx.x & 31;
    if (warp < HH) {
        float s = 0.f;
        #pragma unroll 4
        for (int c = lane; c < DD; c += 32) s += xs[c] * Ws[c * HH + warp];
        #pragma unroll
        for (int o = 16; o > 0; o >>= 1) s += __shfl_xor_sync(0xffffffffu, s, o);
        if (lane == 0) {
            float sig   = 1.f / (1.f + expf(-(s + bs[warp])));
            float denom = expf(sig) + 1.f;
            int b = bi / NN, i = bi % NN;
            g_r[((size_t)b * HH + warp) * NN + i] = expf(-1.f / denom);
        }
    }
}

// ---------------------------------------------------------------------------
// mma.sync bf16 GEMM: C[8192,512] = A(hi+lo) @ Bt(hi+lo)^T (+ bias)
// BM=128 BN=128 BK=32, 256 thr = 8 warps (2 M x 4 N), warp tile 64x32.
// 3-term bf16 split, fp32 accum. Double-buffered cp.async.
// Smem row pad: 40 bf16 (80 B) -> ldmatrix conflict-free.
// ---------------------------------------------------------------------------
#define PAD_ROW  80            // bytes per 32-k row
#define BUF_SZ   (128 * PAD_ROW)   // 10240 bytes per plane-buffer
#define SM_AH    0
#define SM_AL    (2 * BUF_SZ)
#define SM_BH    (4 * BUF_SZ)
#define SM_BL    (6 * BUF_SZ)
#define SM_GTOT  (8 * BUF_SZ)      // 81920 bytes

template<bool BIAS>
__global__ void __launch_bounds__(256, 1)
gemm_mma(const __nv_bfloat16* __restrict__ Ahi, const __nv_bfloat16* __restrict__ Alo,
         const __nv_bfloat16* __restrict__ Bhi, const __nv_bfloat16* __restrict__ Blo,
         const float* __restrict__ bias, float* __restrict__ C)
{
    extern __shared__ char smem[];
    uint32_t sb = smem_u32(smem);
    int tid = threadIdx.x, wid = tid >> 5, lane = tid & 31;
    int wm = wid & 1, wn = wid >> 1;
    int m0 = blockIdx.y * 128, n0 = blockIdx.x * 128;

    float acc[4][4][4];
    #pragma unroll
    for (int a = 0; a < 4; a++)
        #pragma unroll
        for (int b = 0; b < 4; b++)
            #pragma unroll
            for (int c = 0; c < 4; c++) acc[a][b][c] = 0.f;

    // ---- async load of one K-chunk into buffer ----
    auto issue = [&](int ch, int buf) {
        int k0 = ch * 32;
        uint32_t bo = buf * BUF_SZ;
        #pragma unroll
        for (int t = 0; t < 2; t++) {
            int task = t * 256 + tid;          // 0..511
            int row = task >> 2, g = task & 3;
            uint32_t so = bo + row * PAD_ROW + g * 16;
            size_t Aoff = (size_t)(m0 + row) * DD + k0 + g * 8;
            size_t Boff = (size_t)(n0 + row) * DD + k0 + g * 8;
            CP16(sb + SM_AH + so, Ahi + Aoff);
            CP16(sb + SM_AL + so, Alo + Aoff);
            CP16(sb + SM_BH + so, Bhi + Boff);
            CP16(sb + SM_BL + so, Blo + Boff);
        }
        CP_COMMIT();
    };

    issue(0, 0);
    issue(1, 1);

    int arow = lane & 15, ak = (lane >> 4) * 16;
    int brow = (lane & 7) + ((lane >> 4) << 3), bk = ((lane >> 3) & 1) * 16;

    for (int ch = 0; ch < 16; ch++) {
        if (ch < 15) { CP_WAIT(1); } else { CP_WAIT(0); }
        __syncthreads();

        int buf = ch & 1;
        uint32_t aH = sb + SM_AH + buf * BUF_SZ + (wm * 64) * PAD_ROW;
        uint32_t aL = sb + SM_AL + buf * BUF_SZ + (wm * 64) * PAD_ROW;
        uint32_t bH = sb + SM_BH + buf * BUF_SZ + (wn * 32) * PAD_ROW;
        uint32_t bL = sb + SM_BL + buf * BUF_SZ + (wn * 32) * PAD_ROW;

        #pragma unroll
        for (int ks = 0; ks < 2; ks++) {
            int kb = ks * 32;                  // byte offset of k16 step
            uint32_t Ah[4][4], Al[4][4], Bh[4][2], Bl[4][2];
            #pragma unroll
            for (int mi = 0; mi < 4; mi++) {
                uint32_t off = (mi * 16 + arow) * PAD_ROW + kb + ak;
                LDSM_X4(Ah[mi], aH + off);
                LDSM_X4(Al[mi], aL + off);
            }
            #pragma unroll
            for (int nf = 0; nf < 2; nf++) {
                uint32_t off = (nf * 16 + brow) * PAD_ROW + kb + bk;
                uint32_t r[4];
                LDSM_X4(r, bH + off);
                Bh[2 * nf][0] = r[0]; Bh[2 * nf][1] = r[1];
                Bh[2 * nf + 1][0] = r[2]; Bh[2 * nf + 1][1] = r[3];
                LDSM_X4(r, bL + off);
                Bl[2 * nf][0] = r[0]; Bl[2 * nf][1] = r[1];
                Bl[2 * nf + 1][0] = r[2]; Bl[2 * nf + 1][1] = r[3];
            }
            #pragma unroll
            for (int mi = 0; mi < 4; mi++)
                #pragma unroll
                for (int ni = 0; ni < 4; ni++) {
                    MMA16816(acc[mi][ni], Ah[mi], Bh[ni]);
                    MMA16816(acc[mi][ni], Ah[mi], Bl[ni]);
                    MMA16816(acc[mi][ni], Al[mi], Bh[ni]);
                }
        }
        __syncthreads();
        if (ch + 2 < 16) issue(ch + 2, buf);
    }

    // ---- epilogue ----
    #pragma unroll
    for (int mi = 0; mi < 4; mi++) {
        int row = m0 + wm * 64 + mi * 16 + (lane >> 2);
        #pragma unroll
        for (int ni = 0; ni < 4; ni++) {
            int col = n0 + wn * 32 + ni * 8 + 2 * (lane & 3);
            float b0 = 0.f, b1 = 0.f;
            if (BIAS) { b0 = bias[col]; b1 = bias[col + 1]; }
            float2 v0 = make_float2(acc[mi][ni][0] + b0, acc[mi][ni][1] + b1);
            float2 v1 = make_float2(acc[mi][ni][2] + b0, acc[mi][ni][3] + b1);
            *(float2*)(C + (size_t)row * DD + col)       = v0;
            *(float2*)(C + (size_t)(row + 8) * DD + col) = v1;
        }
    }
}

// ---------------------------------------------------------------------------
// Windowed exponential smoothing; emits bf16 hi/lo planes for GEMM2.
// ---------------------------------------------------------------------------
__global__ void __launch_bounds__(512, 2)
attn_kernel()
{
    __shared__ float4 vs[TI + 2 * WIN][DH / 4];   // 160 x 16 float4 = 40 KB

    int bh = blockIdx.y;
    int b  = bh / HH, h = bh % HH;
    int i0 = blockIdx.x * TI;
    const float* Vbase = g_V + (size_t)b * NN * DD + h * DH;

    for (int idx = threadIdx.x; idx < (TI + 2 * WIN) * (DH / 4); idx += blockDim.x) {
        int lr = idx >> 4, c = idx & 15;
        int j = i0 - WIN + lr;
        float4 v = make_float4(0.f, 0.f, 0.f, 0.f);
        if (j >= 0 && j < NN) v = *(const float4*)(Vbase + (size_t)j * DD + c * 4);
        vs[lr][c] = v;
    }
    __syncthreads();

    int il = threadIdx.x >> 4, c = threadIdx.x & 15;
    int i  = i0 + il;
    float r = g_r[(size_t)bh * NN + i];

    int li = il + WIN;
    float4 acc = vs[li][c];
    float z = 1.f, w = 1.f;

    #pragma unroll
    for (int k = 1; k <= WIN; k++) {
        w *= r;
        float4 vl = vs[li - k][c];
        float4 vr = vs[li + k][c];
        acc.x += w * (vl.x + vr.x);
        acc.y += w * (vl.y + vr.y);
        acc.z += w * (vl.z + vr.z);
        acc.w += w * (vl.w + vr.w);
        z += w * ((float)(i - k >= 0) + (float)(i + k < NN));
    }

    float inv = 1.f / z;
    float4 o = make_float4(acc.x * inv, acc.y * inv, acc.z * inv, acc.w * inv);

    size_t ob = ((size_t)b * NN + i) * DD + h * DH + c * 4;
    __nv_bfloat16 h0 = __float2bfloat16(o.x), h1 = __float2bfloat16(o.y);
    __nv_bfloat16 h2 = __float2bfloat16(o.z), h3 = __float2bfloat16(o.w);
    __nv_bfloat162 hp0; hp0.x = h0; hp0.y = h1;
    __nv_bfloat162 hp1; hp1.x = h2; hp1.y = h3;
    __nv_bfloat162 lp0, lp1;
    lp0.x = __float2bfloat16(o.x - __bfloat162float(h0));
    lp0.y = __float2bfloat16(o.y - __bfloat162float(h1));
    lp1.x = __float2bfloat16(o.z - __bfloat162float(h2));
    lp1.y = __float2bfloat16(o.w - __bfloat162float(h3));
    *(__nv_bfloat162*)(g_ahi + ob)     = hp0;
    *(__nv_bfloat162*)(g_ahi + ob + 2) = hp1;
    *(__nv_bfloat162*)(g_alo + ob)     = lp0;
    *(__nv_bfloat162*)(g_alo + ob + 2) = lp1;
}

// ---------------------------------------------------------------------------
// Launch
// ---------------------------------------------------------------------------
extern "C" void kernel_launch(void* const* d_in, const int* in_sizes, int n_in,
                              void* d_out, int out_size)
{
    const float* x     = (const float*)d_in[0];
    const float* W_v   = (const float*)d_in[1];
    const float* W_sig = (const float*)d_in[2];
    const float* b_sig = (const float*)d_in[3];
    const float* W_out = (const float*)d_in[4];
    const float* b_out = (const float*)d_in[5];
    float* out = (float*)d_out;

    float *pV = nullptr;
    __nv_bfloat16 *pxh, *pxl, *pvh, *pvl, *poh, *pol, *pah, *pal;
    cudaGetSymbolAddress((void**)&pV,  g_V);
    cudaGetSymbolAddress((void**)&pxh, g_xhi);
    cudaGetSymbolAddress((void**)&pxl, g_xlo);
    cudaGetSymbolAddress((void**)&pvh, g_Wvth);
    cudaGetSymbolAddress((void**)&pvl, g_Wvtl);
    cudaGetSymbolAddress((void**)&poh, g_Woth);
    cudaGetSymbolAddress((void**)&pol, g_Wotl);
    cudaGetSymbolAddress((void**)&pah, g_ahi);
    cudaGetSymbolAddress((void**)&pal, g_alo);

    cudaFuncSetAttribute(gemm_mma<false>, cudaFuncAttributeMaxDynamicSharedMemorySize, SM_GTOT);
    cudaFuncSetAttribute(gemm_mma<true>,  cudaFuncAttributeMaxDynamicSharedMemorySize, SM_GTOT);

    conv_x_kernel<<<(MTOT * DD / 4 + 255) / 256, 256>>>(x);
    conv_wT_kernel<<<dim3(16, 16), dim3(32, 32)>>>(W_v,   pvh, pvl);
    conv_wT_kernel<<<dim3(16, 16), dim3(32, 32)>>>(W_out, poh, pol);
    sigma_kernel<<<BB * NN, 256>>>(x, W_sig, b_sig);

    gemm_mma<false><<<dim3(4, 64), 256, SM_GTOT>>>(pxh, pxl, pvh, pvl, nullptr, pV);

    attn_kernel<<<dim3(NN / TI, BB * HH), 512>>>();

    gemm_mma<true><<<dim3(4, 64), 256, SM_GTOT>>>(pah, pal, poh, pol, b_out, out);
}